// round 8
// baseline (speedup 1.0000x reference)
#include <cuda_runtime.h>
#include <cuda_bf16.h>
#include <math.h>
#include <stdint.h>

// ---------------------------------------------------------------------------
// ViT attention: TF32 mma.sync with FRAGMENT-MAJOR Q/K/V layouts.
// Projection GEMMs write q/k/v directly in mma fragment order, so the
// attention kernels (rowsum + flash) run with zero shared memory and zero
// block synchronization: fragments come straight from LDG.128/LDG.64.
// B=4, S=2048, E=768, H=12, D=64.
// d_out = attn_output [4,2048,768] ++ attn_weights [4,12,2048,2048].
// ---------------------------------------------------------------------------

#define BATCH     4
#define SEQ       2048
#define EMB       768
#define HEADS     12
#define HDIM      64
#define MTOK      (BATCH * SEQ)
#define BH        (BATCH * HEADS)
#define SCALE_F   0.125f

#define PAD       36

// Fragment-major scratch. Per (b,h): 2048*64 = 131072 floats (1<<17).
// Qf (a-frag):  [s/16][d/8][lane=(s%8)*4+(d%4)][j=(s>>3&1)|((d>>2&1)<<1)]
// Kf (b-frag):  [s/8][d/8][lane=(s%8)*4+(d%4)][j=(d>>2)&1]
// Vf (b-frag):  [s/8][d/8][lane=(d%8)*4+(s%4)][j=(s>>2)&1]
__device__ __align__(16) float g_qf[BH * (1 << 17)];
__device__ __align__(16) float g_kf[BH * (1 << 17)];
__device__ __align__(16) float g_vf[BH * (1 << 17)];
__device__ float g_att[MTOK * EMB];
__device__ float g_inv[BH * SEQ];

// ---------------------------------------------------------------------------
__device__ __forceinline__ void cp16(void* s, const void* g) {
    uint32_t sa = (uint32_t)__cvta_generic_to_shared(s);
    asm volatile("cp.async.cg.shared.global [%0], [%1], 16;\n" :: "r"(sa), "l"(g));
}
__device__ __forceinline__ void cp_commit() {
    asm volatile("cp.async.commit_group;\n" ::: "memory");
}
__device__ __forceinline__ void cp_wait2() {
    asm volatile("cp.async.wait_group 2;\n" ::: "memory");
}

__device__ __forceinline__ float rnd(float x) {
    float r;
    asm("cvt.rna.tf32.f32 %0, %1;" : "=f"(r) : "f"(x));
    return r;
}
__device__ __forceinline__ uint32_t frag(float x) { return __float_as_uint(rnd(x)); }
__device__ __forceinline__ uint32_t u(float x)    { return __float_as_uint(x); }

__device__ __forceinline__ void mma_tf32(float c[4],
                                         uint32_t a0, uint32_t a1, uint32_t a2, uint32_t a3,
                                         uint32_t b0, uint32_t b1) {
    asm volatile(
        "mma.sync.aligned.m16n8k8.row.col.f32.tf32.tf32.f32 "
        "{%0,%1,%2,%3}, {%4,%5,%6,%7}, {%8,%9}, {%0,%1,%2,%3};\n"
        : "+f"(c[0]), "+f"(c[1]), "+f"(c[2]), "+f"(c[3])
        : "r"(a0), "r"(a1), "r"(a2), "r"(a3), "r"(b0), "r"(b1));
}

// frag-layout scatter stores (values must already be tf32-rounded)
template <int MODE>   // 1=Qf, 2=Kf, 3=Vf
__device__ __forceinline__ void store_frag(int bh, int s, int d, float v) {
    size_t base = (size_t)bh << 17;
    if (MODE == 1) {
        int idx = ((((s >> 4) << 3) + (d >> 3)) << 7)
                + ((((s & 7) << 2) | (d & 3)) << 2)
                + (((s >> 3) & 1) | (((d >> 2) & 1) << 1));
        g_qf[base + idx] = v;
    } else if (MODE == 2) {
        int idx = ((((s >> 3) << 3) + (d >> 3)) << 6)
                + ((((s & 7) << 2) | (d & 3)) << 1)
                + ((d >> 2) & 1);
        g_kf[base + idx] = v;
    } else {
        int idx = ((((s >> 3) << 3) + (d >> 3)) << 6)
                + ((((d & 7) << 2) | (s & 3)) << 1)
                + ((s >> 2) & 1);
        g_vf[base + idx] = v;
    }
}

// ---------------------------------------------------------------------------
// Projection GEMM: A[M,K] @ W[N,K]^T + bias.  128x128 tile, 8 warps,
// 3-stage cp.async. MODE 0: plain fp32 store to C (final output).
// MODE 1/2/3: tf32-rounded scatter into g_qf/g_kf/g_vf.
// ---------------------------------------------------------------------------
template <int MODE>
__global__ __launch_bounds__(256, 2)
void gemm_xwT_tc(const float* __restrict__ A,
                 const float* __restrict__ W,
                 const float* __restrict__ bias,
                 float* __restrict__ C,
                 int M, int N, int K) {
    extern __shared__ __align__(16) float sm[];
    float (*As)[128][PAD] = (float (*)[128][PAD])sm;
    float (*Ws)[128][PAD] = (float (*)[128][PAD])(sm + 3 * 128 * PAD);

    const int m0 = blockIdx.y * 128;
    const int n0 = blockIdx.x * 128;
    const int tid = threadIdx.x;
    const int wid = tid >> 5;
    const int lane = tid & 31;
    const int wm = (wid >> 1) * 32;
    const int wn = (wid & 1) * 64;
    const int g = lane >> 2;
    const int t = lane & 3;
    const int nk = K >> 5;

    float acc[2][8][4] = {};

    #pragma unroll
    for (int s = 0; s < 2; s++) {
        const int k0 = s * 32;
        #pragma unroll
        for (int i = 0; i < 4; i++) {
            int idx = tid + i * 256, r = idx >> 3, c4 = idx & 7;
            cp16(&As[s][r][c4 * 4], A + (size_t)(m0 + r) * K + k0 + c4 * 4);
        }
        #pragma unroll
        for (int i = 0; i < 4; i++) {
            int idx = tid + i * 256, r = idx >> 3, c4 = idx & 7;
            cp16(&Ws[s][r][c4 * 4], W + (size_t)(n0 + r) * K + k0 + c4 * 4);
        }
        cp_commit();
    }

    for (int kt = 0; kt < nk; kt++) {
        if (kt + 2 < nk) {
            const int sb = (kt + 2) % 3;
            const int k0 = (kt + 2) * 32;
            #pragma unroll
            for (int i = 0; i < 4; i++) {
                int idx = tid + i * 256, r = idx >> 3, c4 = idx & 7;
                cp16(&As[sb][r][c4 * 4], A + (size_t)(m0 + r) * K + k0 + c4 * 4);
            }
            #pragma unroll
            for (int i = 0; i < 4; i++) {
                int idx = tid + i * 256, r = idx >> 3, c4 = idx & 7;
                cp16(&Ws[sb][r][c4 * 4], W + (size_t)(n0 + r) * K + k0 + c4 * 4);
            }
        }
        cp_commit();
        cp_wait2();
        __syncthreads();

        const int buf = kt % 3;
        #pragma unroll
        for (int kk = 0; kk < 4; kk++) {
            const int kb = kk * 8;
            uint32_t a[2][4], b[8][2];
            #pragma unroll
            for (int mi = 0; mi < 2; mi++) {
                int row = wm + mi * 16;
                a[mi][0] = frag(As[buf][row + g][kb + t]);
                a[mi][1] = frag(As[buf][row + 8 + g][kb + t]);
                a[mi][2] = frag(As[buf][row + g][kb + 4 + t]);
                a[mi][3] = frag(As[buf][row + 8 + g][kb + 4 + t]);
            }
            #pragma unroll
            for (int ni = 0; ni < 8; ni++) {
                int col = wn + ni * 8;
                b[ni][0] = frag(Ws[buf][col + g][kb + t]);
                b[ni][1] = frag(Ws[buf][col + g][kb + 4 + t]);
            }
            #pragma unroll
            for (int mi = 0; mi < 2; mi++)
                #pragma unroll
                for (int ni = 0; ni < 8; ni++)
                    mma_tf32(acc[mi][ni], a[mi][0], a[mi][1], a[mi][2], a[mi][3],
                             b[ni][0], b[ni][1]);
        }
        __syncthreads();
    }

    #pragma unroll
    for (int mi = 0; mi < 2; mi++) {
        #pragma unroll
        for (int ni = 0; ni < 8; ni++) {
            int m = m0 + wm + mi * 16 + g;
            int n = n0 + wn + ni * 8 + t * 2;
            float b0 = __ldg(&bias[n]), b1 = __ldg(&bias[n + 1]);
            float v0 = acc[mi][ni][0] + b0;
            float v1 = acc[mi][ni][1] + b1;
            float v2 = acc[mi][ni][2] + b0;
            float v3 = acc[mi][ni][3] + b1;
            if (MODE == 0) {
                C[(size_t)m * N + n]           = v0;
                C[(size_t)m * N + n + 1]       = v1;
                C[(size_t)(m + 8) * N + n]     = v2;
                C[(size_t)(m + 8) * N + n + 1] = v3;
            } else {
                int bb = m >> 11, s = m & 2047;
                int hh = n >> 6,  d = n & 63;
                int bh = bb * HEADS + hh;
                store_frag<MODE>(bh, s,     d,     rnd(v0));
                store_frag<MODE>(bh, s,     d + 1, rnd(v1));
                store_frag<MODE>(bh, s + 8, d,     rnd(v2));
                store_frag<MODE>(bh, s + 8, d + 1, rnd(v3));
            }
        }
    }
}

// ---------------------------------------------------------------------------
// rowsum: g_inv = 1/rowsum(exp(QK^T*scale)). No smem, no syncs.
// grid (SEQ/128, BH), 256 threads; warp w owns q rows [q0+16w, q0+16w+16).
// ---------------------------------------------------------------------------
__global__ __launch_bounds__(256, 3)
void rowsum_tc() {
    const int bh = blockIdx.y;
    const int q0 = blockIdx.x * 128;
    const int w = threadIdx.x >> 5;
    const int lane = threadIdx.x & 31;
    const int g = lane >> 2;
    const int t = lane & 3;
    const int s16 = (q0 >> 4) + w;

    // Q a-frags: 8 x LDG.128, persist in regs
    const float4* qfp = ((const float4*)g_qf) + ((size_t)bh << 15) + ((s16 * 8) << 5) + lane;
    float4 qf[8];
    #pragma unroll
    for (int d8 = 0; d8 < 8; d8++) qf[d8] = qfp[d8 << 5];

    const float2* kfp = ((const float2*)g_kf) + ((size_t)bh << 16) + lane;

    float rs0 = 0.f, rs1 = 0.f;
    #pragma unroll 2
    for (int s8 = 0; s8 < SEQ / 8; s8++) {
        float sc[4] = {0.f, 0.f, 0.f, 0.f};
        #pragma unroll
        for (int d8 = 0; d8 < 8; d8++) {
            float2 kf = kfp[(s8 * 8 + d8) << 5];
            mma_tf32(sc, u(qf[d8].x), u(qf[d8].y), u(qf[d8].z), u(qf[d8].w),
                     u(kf.x), u(kf.y));
        }
        rs0 += __expf(sc[0] * SCALE_F) + __expf(sc[1] * SCALE_F);
        rs1 += __expf(sc[2] * SCALE_F) + __expf(sc[3] * SCALE_F);
    }

    rs0 += __shfl_xor_sync(0xffffffffu, rs0, 1);
    rs0 += __shfl_xor_sync(0xffffffffu, rs0, 2);
    rs1 += __shfl_xor_sync(0xffffffffu, rs1, 1);
    rs1 += __shfl_xor_sync(0xffffffffu, rs1, 2);

    if (t == 0) {
        g_inv[(size_t)bh * SEQ + q0 + w * 16 + g]     = 1.0f / rs0;
        g_inv[(size_t)bh * SEQ + q0 + w * 16 + 8 + g] = 1.0f / rs1;
    }
}

// ---------------------------------------------------------------------------
// flash: recompute scores, p = exp(s)*inv (written once), O = p @ V -> g_att.
// No smem, no block syncs; c-frag -> a-frag via warp shuffles.
// grid (SEQ/128, BH), 256 threads.
// ---------------------------------------------------------------------------
__global__ __launch_bounds__(256, 2)
void flash_pv_tc(float* __restrict__ wbuf) {
    const int bh = blockIdx.y;
    const int b  = bh / HEADS;
    const int h  = bh % HEADS;
    const int q0 = blockIdx.x * 128;
    const int w = threadIdx.x >> 5;
    const int lane = threadIdx.x & 31;
    const int g = lane >> 2;
    const int t = lane & 3;
    const int qrow = q0 + w * 16;
    const int s16 = qrow >> 4;

    const float4* qfp = ((const float4*)g_qf) + ((size_t)bh << 15) + ((s16 * 8) << 5) + lane;
    float4 qf[8];
    #pragma unroll
    for (int d8 = 0; d8 < 8; d8++) qf[d8] = qfp[d8 << 5];

    const float iv0 = g_inv[(size_t)bh * SEQ + qrow + g];
    const float iv1 = g_inv[(size_t)bh * SEQ + qrow + 8 + g];

    const float2* kfp = ((const float2*)g_kf) + ((size_t)bh << 16) + lane;
    const float2* vfp = ((const float2*)g_vf) + ((size_t)bh << 16) + lane;

    float* prow = wbuf + (size_t)bh * SEQ * SEQ;
    float* p0row = prow + (size_t)(qrow + g) * SEQ + 2 * t;
    float* p1row = prow + (size_t)(qrow + 8 + g) * SEQ + 2 * t;

    const int src_lo = (lane & ~3) | (t >> 1);
    const int src_hi = src_lo + 2;
    const bool odd = (t & 1);

    float o[8][4] = {};

    #pragma unroll 2
    for (int s8 = 0; s8 < SEQ / 8; s8++) {
        float sc[4] = {0.f, 0.f, 0.f, 0.f};
        #pragma unroll
        for (int d8 = 0; d8 < 8; d8++) {
            float2 kf = kfp[(s8 * 8 + d8) << 5];
            mma_tf32(sc, u(qf[d8].x), u(qf[d8].y), u(qf[d8].z), u(qf[d8].w),
                     u(kf.x), u(kf.y));
        }

        float p0 = rnd(__expf(sc[0] * SCALE_F) * iv0);
        float p1 = rnd(__expf(sc[1] * SCALE_F) * iv0);
        float p2 = rnd(__expf(sc[2] * SCALE_F) * iv1);
        float p3 = rnd(__expf(sc[3] * SCALE_F) * iv1);

        *(float2*)(p0row + s8 * 8) = make_float2(p0, p1);
        *(float2*)(p1row + s8 * 8) = make_float2(p2, p3);

        // c-frag (rows g/8+g, cols 2t,2t+1) -> a-frag (cols t, 4+t)
        float e0 = __shfl_sync(0xffffffffu, p0, src_lo);
        float e1 = __shfl_sync(0xffffffffu, p1, src_lo);
        float a0 = odd ? e1 : e0;                         // (g, t)
        float e2 = __shfl_sync(0xffffffffu, p2, src_lo);
        float e3 = __shfl_sync(0xffffffffu, p3, src_lo);
        float a1 = odd ? e3 : e2;                         // (8+g, t)
        float f0 = __shfl_sync(0xffffffffu, p0, src_hi);
        float f1 = __shfl_sync(0xffffffffu, p1, src_hi);
        float a2 = odd ? f1 : f0;                         // (g, 4+t)
        float f2 = __shfl_sync(0xffffffffu, p2, src_hi);
        float f3 = __shfl_sync(0xffffffffu, p3, src_hi);
        float a3 = odd ? f3 : f2;                         // (8+g, 4+t)

        #pragma unroll
        for (int d8 = 0; d8 < 8; d8++) {
            float2 vf = vfp[(s8 * 8 + d8) << 5];
            mma_tf32(o[d8], u(a0), u(a1), u(a2), u(a3), u(vf.x), u(vf.y));
        }
    }

    float* ob0 = g_att + (size_t)(b * SEQ + qrow + g) * EMB + h * HDIM + 2 * t;
    float* ob1 = g_att + (size_t)(b * SEQ + qrow + 8 + g) * EMB + h * HDIM + 2 * t;
    #pragma unroll
    for (int d8 = 0; d8 < 8; d8++) {
        *(float2*)(ob0 + d8 * 8) = make_float2(o[d8][0], o[d8][1]);
        *(float2*)(ob1 + d8 * 8) = make_float2(o[d8][2], o[d8][3]);
    }
}

// ---------------------------------------------------------------------------
// launch
// ---------------------------------------------------------------------------
extern "C" void kernel_launch(void* const* d_in, const int* in_sizes, int n_in,
                              void* d_out, int out_size) {
    (void)in_sizes; (void)n_in; (void)out_size;

    const float* hs = (const float*)d_in[0];
    const float* Wq = (const float*)d_in[1];
    const float* bq = (const float*)d_in[2];
    const float* Wk = (const float*)d_in[3];
    const float* bk = (const float*)d_in[4];
    const float* Wv = (const float*)d_in[5];
    const float* bv = (const float*)d_in[6];
    const float* Wo = (const float*)d_in[7];
    const float* bo = (const float*)d_in[8];

    float* out      = (float*)d_out;
    float* attn_out = out;
    float* wbuf     = out + (size_t)MTOK * EMB;

    float* datt;
    cudaGetSymbolAddress((void**)&datt, g_att);

    const int smem_gemm = (3 * 128 * PAD + 3 * 128 * PAD) * 4;   // 110592

    cudaFuncSetAttribute(gemm_xwT_tc<0>, cudaFuncAttributeMaxDynamicSharedMemorySize, smem_gemm);
    cudaFuncSetAttribute(gemm_xwT_tc<1>, cudaFuncAttributeMaxDynamicSharedMemorySize, smem_gemm);
    cudaFuncSetAttribute(gemm_xwT_tc<2>, cudaFuncAttributeMaxDynamicSharedMemorySize, smem_gemm);
    cudaFuncSetAttribute(gemm_xwT_tc<3>, cudaFuncAttributeMaxDynamicSharedMemorySize, smem_gemm);

    dim3 gproj(EMB / 128, MTOK / 128);      // (6, 64)

    gemm_xwT_tc<1><<<gproj, 256, smem_gemm>>>(hs, Wq, bq, nullptr, MTOK, EMB, EMB);
    gemm_xwT_tc<2><<<gproj, 256, smem_gemm>>>(hs, Wk, bk, nullptr, MTOK, EMB, EMB);
    gemm_xwT_tc<3><<<gproj, 256, smem_gemm>>>(hs, Wv, bv, nullptr, MTOK, EMB, EMB);

    rowsum_tc<<<dim3(SEQ / 128, BH), 256>>>();

    flash_pv_tc<<<dim3(SEQ / 128, BH), 256>>>(wbuf);

    gemm_xwT_tc<0><<<gproj, 256, smem_gemm>>>(datt, Wo, bo, attn_out, MTOK, EMB, EMB);
}

// round 9
// speedup vs baseline: 1.3211x; 1.3211x over previous
#include <cuda_runtime.h>
#include <cuda_bf16.h>
#include <math.h>
#include <stdint.h>

// ---------------------------------------------------------------------------
// ViT attention: TF32 mma.sync, ALL operands pre-rounded to tf32 in gmem
// (zero cvt in any mainloop), cp.async pipelines, flash-style attention.
// B=4, S=2048, E=768, H=12, D=64.
// d_out = attn_output [4,2048,768] ++ attn_weights [4,12,2048,2048].
// ---------------------------------------------------------------------------

#define BATCH     4
#define SEQ       2048
#define EMB       768
#define HEADS     12
#define HDIM      64
#define MTOK      (BATCH * SEQ)
#define BH        (BATCH * HEADS)
#define SCALE_F   0.125f

#define PAD       36
#define STR       68
#define VSTR      72

// Scratch (device globals — no allocation allowed). All hold tf32-rounded.
__device__ float g_q[MTOK * EMB];
__device__ float g_k[MTOK * EMB];
__device__ float g_v[MTOK * EMB];
__device__ float g_att[MTOK * EMB];
__device__ float g_inv[BH * SEQ];
__device__ float g_hsr[MTOK * EMB];      // rounded hidden_states
__device__ float g_wq[EMB * EMB];
__device__ float g_wk[EMB * EMB];
__device__ float g_wv[EMB * EMB];
__device__ float g_wo[EMB * EMB];

// ---------------------------------------------------------------------------
__device__ __forceinline__ void cp16(void* s, const void* g) {
    uint32_t sa = (uint32_t)__cvta_generic_to_shared(s);
    asm volatile("cp.async.cg.shared.global [%0], [%1], 16;\n" :: "r"(sa), "l"(g));
}
__device__ __forceinline__ void cp_commit() {
    asm volatile("cp.async.commit_group;\n" ::: "memory");
}
__device__ __forceinline__ void cp_wait2() {
    asm volatile("cp.async.wait_group 2;\n" ::: "memory");
}
__device__ __forceinline__ void cp_wait1() {
    asm volatile("cp.async.wait_group 1;\n" ::: "memory");
}
__device__ __forceinline__ void cp_wait0() {
    asm volatile("cp.async.wait_group 0;\n" ::: "memory");
}

__device__ __forceinline__ float rnd(float x) {
    float r;
    asm("cvt.rna.tf32.f32 %0, %1;" : "=f"(r) : "f"(x));
    return r;
}
__device__ __forceinline__ uint32_t raw(float x) { return __float_as_uint(x); }

__device__ __forceinline__ void mma_tf32(float c[4],
                                         uint32_t a0, uint32_t a1, uint32_t a2, uint32_t a3,
                                         uint32_t b0, uint32_t b1) {
    asm volatile(
        "mma.sync.aligned.m16n8k8.row.col.f32.tf32.tf32.f32 "
        "{%0,%1,%2,%3}, {%4,%5,%6,%7}, {%8,%9}, {%0,%1,%2,%3};\n"
        : "+f"(c[0]), "+f"(c[1]), "+f"(c[2]), "+f"(c[3])
        : "r"(a0), "r"(a1), "r"(a2), "r"(a3), "r"(b0), "r"(b1));
}

// ---------------------------------------------------------------------------
// Pre-rounding: out[i] = tf32_rn(in[i]) (vectorized).
// ---------------------------------------------------------------------------
__global__ void round_tf32_kernel(const float4* __restrict__ in,
                                  float4* __restrict__ out, int n4) {
    int i = blockIdx.x * blockDim.x + threadIdx.x;
    if (i < n4) {
        float4 v = in[i];
        v.x = rnd(v.x); v.y = rnd(v.y); v.z = rnd(v.z); v.w = rnd(v.w);
        out[i] = v;
    }
}

// ---------------------------------------------------------------------------
// Projection GEMM: C = A @ W^T + bias.  A and W pre-rounded tf32 => raw
// fragment loads. 128x128 tile, 8 warps (4m x 2n), 3-stage cp.async.
// ROUND_OUT: store tf32-rounded (q/k/v); else plain fp32 (final output).
// ---------------------------------------------------------------------------
template <bool ROUND_OUT>
__global__ __launch_bounds__(256, 2)
void gemm_xwT_tc(const float* __restrict__ A,
                 const float* __restrict__ W,
                 const float* __restrict__ bias,
                 float* __restrict__ C,
                 int M, int N, int K) {
    extern __shared__ __align__(16) float sm[];
    float (*As)[128][PAD] = (float (*)[128][PAD])sm;
    float (*Ws)[128][PAD] = (float (*)[128][PAD])(sm + 3 * 128 * PAD);

    const int m0 = blockIdx.y * 128;
    const int n0 = blockIdx.x * 128;
    const int tid = threadIdx.x;
    const int wid = tid >> 5;
    const int lane = tid & 31;
    const int wm = (wid >> 1) * 32;
    const int wn = (wid & 1) * 64;
    const int g = lane >> 2;
    const int t = lane & 3;
    const int nk = K >> 5;

    float acc[2][8][4] = {};

    #pragma unroll
    for (int s = 0; s < 2; s++) {
        const int k0 = s * 32;
        #pragma unroll
        for (int i = 0; i < 4; i++) {
            int idx = tid + i * 256, r = idx >> 3, c4 = idx & 7;
            cp16(&As[s][r][c4 * 4], A + (size_t)(m0 + r) * K + k0 + c4 * 4);
        }
        #pragma unroll
        for (int i = 0; i < 4; i++) {
            int idx = tid + i * 256, r = idx >> 3, c4 = idx & 7;
            cp16(&Ws[s][r][c4 * 4], W + (size_t)(n0 + r) * K + k0 + c4 * 4);
        }
        cp_commit();
    }

    for (int kt = 0; kt < nk; kt++) {
        if (kt + 2 < nk) {
            const int sb = (kt + 2) % 3;
            const int k0 = (kt + 2) * 32;
            #pragma unroll
            for (int i = 0; i < 4; i++) {
                int idx = tid + i * 256, r = idx >> 3, c4 = idx & 7;
                cp16(&As[sb][r][c4 * 4], A + (size_t)(m0 + r) * K + k0 + c4 * 4);
            }
            #pragma unroll
            for (int i = 0; i < 4; i++) {
                int idx = tid + i * 256, r = idx >> 3, c4 = idx & 7;
                cp16(&Ws[sb][r][c4 * 4], W + (size_t)(n0 + r) * K + k0 + c4 * 4);
            }
        }
        cp_commit();
        cp_wait2();
        __syncthreads();

        const int buf = kt % 3;
        #pragma unroll
        for (int kk = 0; kk < 4; kk++) {
            const int kb = kk * 8;
            uint32_t a[2][4], b[8][2];
            #pragma unroll
            for (int mi = 0; mi < 2; mi++) {
                int row = wm + mi * 16;
                a[mi][0] = raw(As[buf][row + g][kb + t]);
                a[mi][1] = raw(As[buf][row + 8 + g][kb + t]);
                a[mi][2] = raw(As[buf][row + g][kb + 4 + t]);
                a[mi][3] = raw(As[buf][row + 8 + g][kb + 4 + t]);
            }
            #pragma unroll
            for (int ni = 0; ni < 8; ni++) {
                int col = wn + ni * 8;
                b[ni][0] = raw(Ws[buf][col + g][kb + t]);
                b[ni][1] = raw(Ws[buf][col + g][kb + 4 + t]);
            }
            #pragma unroll
            for (int mi = 0; mi < 2; mi++)
                #pragma unroll
                for (int ni = 0; ni < 8; ni++)
                    mma_tf32(acc[mi][ni], a[mi][0], a[mi][1], a[mi][2], a[mi][3],
                             b[ni][0], b[ni][1]);
        }
        __syncthreads();
    }

    #pragma unroll
    for (int mi = 0; mi < 2; mi++) {
        #pragma unroll
        for (int ni = 0; ni < 8; ni++) {
            int m = m0 + wm + mi * 16 + g;
            int n = n0 + wn + ni * 8 + t * 2;
            float b0 = __ldg(&bias[n]), b1 = __ldg(&bias[n + 1]);
            float v0 = acc[mi][ni][0] + b0;
            float v1 = acc[mi][ni][1] + b1;
            float v2 = acc[mi][ni][2] + b0;
            float v3 = acc[mi][ni][3] + b1;
            if (ROUND_OUT) { v0 = rnd(v0); v1 = rnd(v1); v2 = rnd(v2); v3 = rnd(v3); }
            C[(size_t)m * N + n]           = v0;
            C[(size_t)m * N + n + 1]       = v1;
            C[(size_t)(m + 8) * N + n]     = v2;
            C[(size_t)(m + 8) * N + n + 1] = v3;
        }
    }
}

// ---------------------------------------------------------------------------
// Kernel A: row sums of exp(QK^T * scale) -> g_inv = 1/sum.
// ---------------------------------------------------------------------------
__global__ __launch_bounds__(256, 3)
void rowsum_tc() {
    extern __shared__ __align__(16) float sm[];
    float* Qs = sm;                       // [128][STR]
    float* Ks = sm + 128 * STR;           // [2][64][STR]
    __shared__ float s_red[128];

    const int bh = blockIdx.y;
    const int b  = bh / HEADS;
    const int h  = bh % HEADS;
    const int q0 = blockIdx.x * 128;
    const int tid = threadIdx.x;
    const int wid = tid >> 5;
    const int lane = tid & 31;
    const int wm = (wid >> 1) * 32;
    const int wn = (wid & 1) * 32;
    const int g = lane >> 2;
    const int t = lane & 3;

    if (tid < 128) s_red[tid] = 0.f;

    #pragma unroll
    for (int i = 0; i < 8; i++) {
        int idx = tid + i * 256, r = idx >> 4, c4 = idx & 15;
        cp16(&Qs[r * STR + c4 * 4],
             g_q + (size_t)(b * SEQ + q0 + r) * EMB + h * HDIM + c4 * 4);
    }
    #pragma unroll
    for (int i = 0; i < 4; i++) {
        int idx = tid + i * 256, r = idx >> 4, c4 = idx & 15;
        cp16(&Ks[r * STR + c4 * 4],
             g_k + (size_t)(b * SEQ + r) * EMB + h * HDIM + c4 * 4);
    }
    cp_commit();

    float rsum[2][2] = {};

    for (int kt = 0; kt < SEQ / 64; kt++) {
        if (kt + 1 < SEQ / 64) {
            float* Kn = Ks + ((kt + 1) & 1) * 64 * STR;
            const int r0 = (kt + 1) * 64;
            #pragma unroll
            for (int i = 0; i < 4; i++) {
                int idx = tid + i * 256, r = idx >> 4, c4 = idx & 15;
                cp16(&Kn[r * STR + c4 * 4],
                     g_k + (size_t)(b * SEQ + r0 + r) * EMB + h * HDIM + c4 * 4);
            }
            cp_commit();
            cp_wait1();
        } else {
            cp_wait0();
        }
        __syncthreads();

        const float* Kb = Ks + (kt & 1) * 64 * STR;
        float acc[2][4][4] = {};

        #pragma unroll
        for (int c0 = 0; c0 < 64; c0 += 32) {
            #pragma unroll
            for (int kk = 0; kk < 4; kk++) {
                const int kb = c0 + kk * 8;
                uint32_t a[2][4], bb[4][2];
                #pragma unroll
                for (int mi = 0; mi < 2; mi++) {
                    int row = wm + mi * 16;
                    a[mi][0] = raw(Qs[(row + g) * STR + kb + t]);
                    a[mi][1] = raw(Qs[(row + 8 + g) * STR + kb + t]);
                    a[mi][2] = raw(Qs[(row + g) * STR + kb + 4 + t]);
                    a[mi][3] = raw(Qs[(row + 8 + g) * STR + kb + 4 + t]);
                }
                #pragma unroll
                for (int ni = 0; ni < 4; ni++) {
                    int col = wn + ni * 8;
                    bb[ni][0] = raw(Kb[(col + g) * STR + kb + t]);
                    bb[ni][1] = raw(Kb[(col + g) * STR + kb + 4 + t]);
                }
                #pragma unroll
                for (int mi = 0; mi < 2; mi++)
                    #pragma unroll
                    for (int ni = 0; ni < 4; ni++)
                        mma_tf32(acc[mi][ni], a[mi][0], a[mi][1], a[mi][2], a[mi][3],
                                 bb[ni][0], bb[ni][1]);
            }
        }

        #pragma unroll
        for (int mi = 0; mi < 2; mi++)
            #pragma unroll
            for (int ni = 0; ni < 4; ni++) {
                rsum[mi][0] += __expf(acc[mi][ni][0] * SCALE_F)
                             + __expf(acc[mi][ni][1] * SCALE_F);
                rsum[mi][1] += __expf(acc[mi][ni][2] * SCALE_F)
                             + __expf(acc[mi][ni][3] * SCALE_F);
            }
        __syncthreads();
    }

    #pragma unroll
    for (int mi = 0; mi < 2; mi++)
        #pragma unroll
        for (int j = 0; j < 2; j++) {
            rsum[mi][j] += __shfl_xor_sync(0xffffffffu, rsum[mi][j], 1);
            rsum[mi][j] += __shfl_xor_sync(0xffffffffu, rsum[mi][j], 2);
        }

    if (t == 0) {
        #pragma unroll
        for (int mi = 0; mi < 2; mi++) {
            atomicAdd(&s_red[wm + mi * 16 + g],     rsum[mi][0]);
            atomicAdd(&s_red[wm + mi * 16 + 8 + g], rsum[mi][1]);
        }
    }
    __syncthreads();
    if (tid < 128)
        g_inv[(size_t)bh * SEQ + q0 + tid] = 1.0f / s_red[tid];
}

// ---------------------------------------------------------------------------
// Kernel B: flash pass. Recompute scores, p = exp(s)*inv (tf32-rounded in
// smem), write p once, accumulate O = p @ V.
// ---------------------------------------------------------------------------
__global__ __launch_bounds__(256, 2)
void flash_pv_tc(float* __restrict__ wbuf) {
    extern __shared__ __align__(16) float sm[];
    float* Qs = sm;                               // [64][STR]
    float* Ks = Qs + 64 * STR;                    // [2][64][STR]
    float* Vs = Ks + 2 * 64 * STR;                // [2][64][VSTR]
    float* Ps = Vs + 2 * 64 * VSTR;               // [64][STR]

    const int bh = blockIdx.y;
    const int b  = bh / HEADS;
    const int h  = bh % HEADS;
    const int q0 = blockIdx.x * 64;
    const int tid = threadIdx.x;
    const int wid = tid >> 5;
    const int lane = tid & 31;
    const int wm = (wid >> 2) * 32;
    const int wn = (wid & 3) * 16;
    const int g = lane >> 2;
    const int t = lane & 3;

    float iv[2][2];
    #pragma unroll
    for (int mi = 0; mi < 2; mi++) {
        iv[mi][0] = g_inv[(size_t)bh * SEQ + q0 + wm + mi * 16 + g];
        iv[mi][1] = g_inv[(size_t)bh * SEQ + q0 + wm + mi * 16 + 8 + g];
    }

    #pragma unroll
    for (int i = 0; i < 4; i++) {
        int idx = tid + i * 256, r = idx >> 4, c4 = idx & 15;
        cp16(&Qs[r * STR + c4 * 4],
             g_q + (size_t)(b * SEQ + q0 + r) * EMB + h * HDIM + c4 * 4);
    }
    #pragma unroll
    for (int i = 0; i < 4; i++) {
        int idx = tid + i * 256, r = idx >> 4, c4 = idx & 15;
        cp16(&Ks[r * STR + c4 * 4],
             g_k + (size_t)(b * SEQ + r) * EMB + h * HDIM + c4 * 4);
        cp16(&Vs[r * VSTR + c4 * 4],
             g_v + (size_t)(b * SEQ + r) * EMB + h * HDIM + c4 * 4);
    }
    cp_commit();

    float* prow = wbuf + (size_t)bh * SEQ * SEQ;
    float acc_o[2][2][4] = {};

    for (int kt = 0; kt < SEQ / 64; kt++) {
        if (kt + 1 < SEQ / 64) {
            const int nb = (kt + 1) & 1;
            const int r0 = (kt + 1) * 64;
            float* Kn = Ks + nb * 64 * STR;
            float* Vn = Vs + nb * 64 * VSTR;
            #pragma unroll
            for (int i = 0; i < 4; i++) {
                int idx = tid + i * 256, r = idx >> 4, c4 = idx & 15;
                cp16(&Kn[r * STR + c4 * 4],
                     g_k + (size_t)(b * SEQ + r0 + r) * EMB + h * HDIM + c4 * 4);
                cp16(&Vn[r * VSTR + c4 * 4],
                     g_v + (size_t)(b * SEQ + r0 + r) * EMB + h * HDIM + c4 * 4);
            }
            cp_commit();
            cp_wait1();
        } else {
            cp_wait0();
        }
        __syncthreads();

        const float* Kb = Ks + (kt & 1) * 64 * STR;
        const float* Vb = Vs + (kt & 1) * 64 * VSTR;

        float acc_s[2][2][4] = {};
        #pragma unroll
        for (int c0 = 0; c0 < 64; c0 += 32) {
            #pragma unroll
            for (int kk = 0; kk < 4; kk++) {
                const int kb = c0 + kk * 8;
                uint32_t a[2][4], bb[2][2];
                #pragma unroll
                for (int mi = 0; mi < 2; mi++) {
                    int row = wm + mi * 16;
                    a[mi][0] = raw(Qs[(row + g) * STR + kb + t]);
                    a[mi][1] = raw(Qs[(row + 8 + g) * STR + kb + t]);
                    a[mi][2] = raw(Qs[(row + g) * STR + kb + 4 + t]);
                    a[mi][3] = raw(Qs[(row + 8 + g) * STR + kb + 4 + t]);
                }
                #pragma unroll
                for (int ni = 0; ni < 2; ni++) {
                    int col = wn + ni * 8;
                    bb[ni][0] = raw(Kb[(col + g) * STR + kb + t]);
                    bb[ni][1] = raw(Kb[(col + g) * STR + kb + 4 + t]);
                }
                #pragma unroll
                for (int mi = 0; mi < 2; mi++)
                    #pragma unroll
                    for (int ni = 0; ni < 2; ni++)
                        mma_tf32(acc_s[mi][ni], a[mi][0], a[mi][1], a[mi][2], a[mi][3],
                                 bb[ni][0], bb[ni][1]);
            }
        }

        #pragma unroll
        for (int mi = 0; mi < 2; mi++) {
            #pragma unroll
            for (int ni = 0; ni < 2; ni++) {
                int m = wm + mi * 16 + g;
                int c = wn + ni * 8 + t * 2;
                Ps[m * STR + c]           = rnd(__expf(acc_s[mi][ni][0] * SCALE_F) * iv[mi][0]);
                Ps[m * STR + c + 1]       = rnd(__expf(acc_s[mi][ni][1] * SCALE_F) * iv[mi][0]);
                Ps[(m + 8) * STR + c]     = rnd(__expf(acc_s[mi][ni][2] * SCALE_F) * iv[mi][1]);
                Ps[(m + 8) * STR + c + 1] = rnd(__expf(acc_s[mi][ni][3] * SCALE_F) * iv[mi][1]);
            }
        }
        __syncthreads();

        #pragma unroll
        for (int i = 0; i < 4; i++) {
            int idx = tid + i * 256, r = idx >> 4, c4 = idx & 15;
            *(float4*)&prow[(size_t)(q0 + r) * SEQ + kt * 64 + c4 * 4] =
                *(const float4*)&Ps[r * STR + c4 * 4];
        }

        #pragma unroll
        for (int c0 = 0; c0 < 64; c0 += 32) {
            #pragma unroll
            for (int kk = 0; kk < 4; kk++) {
                const int kb = c0 + kk * 8;
                uint32_t a[2][4], bb[2][2];
                #pragma unroll
                for (int mi = 0; mi < 2; mi++) {
                    int row = wm + mi * 16;
                    a[mi][0] = raw(Ps[(row + g) * STR + kb + t]);
                    a[mi][1] = raw(Ps[(row + 8 + g) * STR + kb + t]);
                    a[mi][2] = raw(Ps[(row + g) * STR + kb + 4 + t]);
                    a[mi][3] = raw(Ps[(row + 8 + g) * STR + kb + 4 + t]);
                }
                #pragma unroll
                for (int ni = 0; ni < 2; ni++) {
                    int col = wn + ni * 8;
                    bb[ni][0] = raw(Vb[(kb + t) * VSTR + col + g]);
                    bb[ni][1] = raw(Vb[(kb + 4 + t) * VSTR + col + g]);
                }
                #pragma unroll
                for (int mi = 0; mi < 2; mi++)
                    #pragma unroll
                    for (int ni = 0; ni < 2; ni++)
                        mma_tf32(acc_o[mi][ni], a[mi][0], a[mi][1], a[mi][2], a[mi][3],
                                 bb[ni][0], bb[ni][1]);
            }
        }
        __syncthreads();
    }

    #pragma unroll
    for (int mi = 0; mi < 2; mi++) {
        #pragma unroll
        for (int ni = 0; ni < 2; ni++) {
            int m = q0 + wm + mi * 16 + g;
            int d = wn + ni * 8 + t * 2;
            g_att[(size_t)(b * SEQ + m) * EMB + h * HDIM + d]         = rnd(acc_o[mi][ni][0]);
            g_att[(size_t)(b * SEQ + m) * EMB + h * HDIM + d + 1]     = rnd(acc_o[mi][ni][1]);
            g_att[(size_t)(b * SEQ + m + 8) * EMB + h * HDIM + d]     = rnd(acc_o[mi][ni][2]);
            g_att[(size_t)(b * SEQ + m + 8) * EMB + h * HDIM + d + 1] = rnd(acc_o[mi][ni][3]);
        }
    }
}

// ---------------------------------------------------------------------------
// launch
// ---------------------------------------------------------------------------
extern "C" void kernel_launch(void* const* d_in, const int* in_sizes, int n_in,
                              void* d_out, int out_size) {
    (void)in_sizes; (void)n_in; (void)out_size;

    const float* hs = (const float*)d_in[0];
    const float* Wq = (const float*)d_in[1];
    const float* bq = (const float*)d_in[2];
    const float* Wk = (const float*)d_in[3];
    const float* bk = (const float*)d_in[4];
    const float* Wv = (const float*)d_in[5];
    const float* bv = (const float*)d_in[6];
    const float* Wo = (const float*)d_in[7];
    const float* bo = (const float*)d_in[8];

    float* out      = (float*)d_out;
    float* attn_out = out;
    float* wbuf     = out + (size_t)MTOK * EMB;

    float* dq, * dk, * dv, * datt, * dhsr, * dwq, * dwk, * dwv, * dwo;
    cudaGetSymbolAddress((void**)&dq,   g_q);
    cudaGetSymbolAddress((void**)&dk,   g_k);
    cudaGetSymbolAddress((void**)&dv,   g_v);
    cudaGetSymbolAddress((void**)&datt, g_att);
    cudaGetSymbolAddress((void**)&dhsr, g_hsr);
    cudaGetSymbolAddress((void**)&dwq,  g_wq);
    cudaGetSymbolAddress((void**)&dwk,  g_wk);
    cudaGetSymbolAddress((void**)&dwv,  g_wv);
    cudaGetSymbolAddress((void**)&dwo,  g_wo);

    const int smem_gemm  = (3 * 128 * PAD + 3 * 128 * PAD) * 4;                       // 110592
    const int smem_rsum  = (128 * STR + 2 * 64 * STR) * 4;                            // 69632
    const int smem_flash = (64 * STR + 2 * 64 * STR + 2 * 64 * VSTR + 64 * STR) * 4;  // 106496

    cudaFuncSetAttribute(gemm_xwT_tc<true>,  cudaFuncAttributeMaxDynamicSharedMemorySize, smem_gemm);
    cudaFuncSetAttribute(gemm_xwT_tc<false>, cudaFuncAttributeMaxDynamicSharedMemorySize, smem_gemm);
    cudaFuncSetAttribute(rowsum_tc,   cudaFuncAttributeMaxDynamicSharedMemorySize, smem_rsum);
    cudaFuncSetAttribute(flash_pv_tc, cudaFuncAttributeMaxDynamicSharedMemorySize, smem_flash);

    // pre-round hs and weights to tf32 (idempotent w.r.t. fragment cvt)
    const int n4_hs = MTOK * EMB / 4;     // 1572864
    const int n4_w  = EMB * EMB / 4;      // 147456
    round_tf32_kernel<<<(n4_hs + 255) / 256, 256>>>((const float4*)hs, (float4*)dhsr, n4_hs);
    round_tf32_kernel<<<(n4_w + 255) / 256, 256>>>((const float4*)Wq, (float4*)dwq, n4_w);
    round_tf32_kernel<<<(n4_w + 255) / 256, 256>>>((const float4*)Wk, (float4*)dwk, n4_w);
    round_tf32_kernel<<<(n4_w + 255) / 256, 256>>>((const float4*)Wv, (float4*)dwv, n4_w);
    round_tf32_kernel<<<(n4_w + 255) / 256, 256>>>((const float4*)Wo, (float4*)dwo, n4_w);

    dim3 gproj(EMB / 128, MTOK / 128);      // (6, 64)

    gemm_xwT_tc<true><<<gproj, 256, smem_gemm>>>(dhsr, dwq, bq, dq, MTOK, EMB, EMB);
    gemm_xwT_tc<true><<<gproj, 256, smem_gemm>>>(dhsr, dwk, bk, dk, MTOK, EMB, EMB);
    gemm_xwT_tc<true><<<gproj, 256, smem_gemm>>>(dhsr, dwv, bv, dv, MTOK, EMB, EMB);

    rowsum_tc<<<dim3(SEQ / 128, BH), 256, smem_rsum>>>();

    flash_pv_tc<<<dim3(SEQ / 64, BH), 256, smem_flash>>>(wbuf);

    // g_att is already tf32-rounded by flash epilogue; Wo pre-rounded.
    gemm_xwT_tc<false><<<gproj, 256, smem_gemm>>>(datt, dwo, bo, attn_out, MTOK, EMB, EMB);
}

// round 10
// speedup vs baseline: 1.4138x; 1.0702x over previous
#include <cuda_runtime.h>
#include <cuda_bf16.h>
#include <math.h>
#include <stdint.h>

// ---------------------------------------------------------------------------
// ViT attention: TF32 mma.sync, ALL operands pre-rounded to tf32 in gmem,
// cp.async pipelines, flash-style attention with Q a-fragments held in
// registers (zero a-LDS in the attention mainloops).
// B=4, S=2048, E=768, H=12, D=64.
// d_out = attn_output [4,2048,768] ++ attn_weights [4,12,2048,2048].
// ---------------------------------------------------------------------------

#define BATCH     4
#define SEQ       2048
#define EMB       768
#define HEADS     12
#define HDIM      64
#define MTOK      (BATCH * SEQ)
#define BH        (BATCH * HEADS)
#define SCALE_F   0.125f

#define PAD       36
#define STR       68
#define VSTR      72

// Scratch (device globals — no allocation allowed). All hold tf32-rounded.
__device__ float g_q[MTOK * EMB];
__device__ float g_k[MTOK * EMB];
__device__ float g_v[MTOK * EMB];
__device__ float g_att[MTOK * EMB];
__device__ float g_inv[BH * SEQ];
__device__ float g_hsr[MTOK * EMB];      // rounded hidden_states
__device__ float g_wq[EMB * EMB];
__device__ float g_wk[EMB * EMB];
__device__ float g_wv[EMB * EMB];
__device__ float g_wo[EMB * EMB];

// ---------------------------------------------------------------------------
__device__ __forceinline__ void cp16(void* s, const void* g) {
    uint32_t sa = (uint32_t)__cvta_generic_to_shared(s);
    asm volatile("cp.async.cg.shared.global [%0], [%1], 16;\n" :: "r"(sa), "l"(g));
}
__device__ __forceinline__ void cp_commit() {
    asm volatile("cp.async.commit_group;\n" ::: "memory");
}
__device__ __forceinline__ void cp_wait2() {
    asm volatile("cp.async.wait_group 2;\n" ::: "memory");
}
__device__ __forceinline__ void cp_wait1() {
    asm volatile("cp.async.wait_group 1;\n" ::: "memory");
}
__device__ __forceinline__ void cp_wait0() {
    asm volatile("cp.async.wait_group 0;\n" ::: "memory");
}

__device__ __forceinline__ float rnd(float x) {
    float r;
    asm("cvt.rna.tf32.f32 %0, %1;" : "=f"(r) : "f"(x));
    return r;
}
__device__ __forceinline__ uint32_t raw(float x) { return __float_as_uint(x); }

__device__ __forceinline__ void mma_tf32(float c[4],
                                         uint32_t a0, uint32_t a1, uint32_t a2, uint32_t a3,
                                         uint32_t b0, uint32_t b1) {
    asm volatile(
        "mma.sync.aligned.m16n8k8.row.col.f32.tf32.tf32.f32 "
        "{%0,%1,%2,%3}, {%4,%5,%6,%7}, {%8,%9}, {%0,%1,%2,%3};\n"
        : "+f"(c[0]), "+f"(c[1]), "+f"(c[2]), "+f"(c[3])
        : "r"(a0), "r"(a1), "r"(a2), "r"(a3), "r"(b0), "r"(b1));
}

// ---------------------------------------------------------------------------
// Pre-rounding: out[i] = tf32_rn(in[i]) (vectorized).
// ---------------------------------------------------------------------------
__global__ void round_tf32_kernel(const float4* __restrict__ in,
                                  float4* __restrict__ out, int n4) {
    int i = blockIdx.x * blockDim.x + threadIdx.x;
    if (i < n4) {
        float4 v = in[i];
        v.x = rnd(v.x); v.y = rnd(v.y); v.z = rnd(v.z); v.w = rnd(v.w);
        out[i] = v;
    }
}

// ---------------------------------------------------------------------------
// Projection GEMM (unchanged from R9): C = A @ W^T + bias, pre-rounded tf32
// operands, 128x128 tile, 8 warps, 3-stage cp.async.
// ---------------------------------------------------------------------------
template <bool ROUND_OUT>
__global__ __launch_bounds__(256, 2)
void gemm_xwT_tc(const float* __restrict__ A,
                 const float* __restrict__ W,
                 const float* __restrict__ bias,
                 float* __restrict__ C,
                 int M, int N, int K) {
    extern __shared__ __align__(16) float sm[];
    float (*As)[128][PAD] = (float (*)[128][PAD])sm;
    float (*Ws)[128][PAD] = (float (*)[128][PAD])(sm + 3 * 128 * PAD);

    const int m0 = blockIdx.y * 128;
    const int n0 = blockIdx.x * 128;
    const int tid = threadIdx.x;
    const int wid = tid >> 5;
    const int lane = tid & 31;
    const int wm = (wid >> 1) * 32;
    const int wn = (wid & 1) * 64;
    const int g = lane >> 2;
    const int t = lane & 3;
    const int nk = K >> 5;

    float acc[2][8][4] = {};

    #pragma unroll
    for (int s = 0; s < 2; s++) {
        const int k0 = s * 32;
        #pragma unroll
        for (int i = 0; i < 4; i++) {
            int idx = tid + i * 256, r = idx >> 3, c4 = idx & 7;
            cp16(&As[s][r][c4 * 4], A + (size_t)(m0 + r) * K + k0 + c4 * 4);
        }
        #pragma unroll
        for (int i = 0; i < 4; i++) {
            int idx = tid + i * 256, r = idx >> 3, c4 = idx & 7;
            cp16(&Ws[s][r][c4 * 4], W + (size_t)(n0 + r) * K + k0 + c4 * 4);
        }
        cp_commit();
    }

    for (int kt = 0; kt < nk; kt++) {
        if (kt + 2 < nk) {
            const int sb = (kt + 2) % 3;
            const int k0 = (kt + 2) * 32;
            #pragma unroll
            for (int i = 0; i < 4; i++) {
                int idx = tid + i * 256, r = idx >> 3, c4 = idx & 7;
                cp16(&As[sb][r][c4 * 4], A + (size_t)(m0 + r) * K + k0 + c4 * 4);
            }
            #pragma unroll
            for (int i = 0; i < 4; i++) {
                int idx = tid + i * 256, r = idx >> 3, c4 = idx & 7;
                cp16(&Ws[sb][r][c4 * 4], W + (size_t)(n0 + r) * K + k0 + c4 * 4);
            }
        }
        cp_commit();
        cp_wait2();
        __syncthreads();

        const int buf = kt % 3;
        #pragma unroll
        for (int kk = 0; kk < 4; kk++) {
            const int kb = kk * 8;
            uint32_t a[2][4], b[8][2];
            #pragma unroll
            for (int mi = 0; mi < 2; mi++) {
                int row = wm + mi * 16;
                a[mi][0] = raw(As[buf][row + g][kb + t]);
                a[mi][1] = raw(As[buf][row + 8 + g][kb + t]);
                a[mi][2] = raw(As[buf][row + g][kb + 4 + t]);
                a[mi][3] = raw(As[buf][row + 8 + g][kb + 4 + t]);
            }
            #pragma unroll
            for (int ni = 0; ni < 8; ni++) {
                int col = wn + ni * 8;
                b[ni][0] = raw(Ws[buf][col + g][kb + t]);
                b[ni][1] = raw(Ws[buf][col + g][kb + 4 + t]);
            }
            #pragma unroll
            for (int mi = 0; mi < 2; mi++)
                #pragma unroll
                for (int ni = 0; ni < 8; ni++)
                    mma_tf32(acc[mi][ni], a[mi][0], a[mi][1], a[mi][2], a[mi][3],
                             b[ni][0], b[ni][1]);
        }
        __syncthreads();
    }

    #pragma unroll
    for (int mi = 0; mi < 2; mi++) {
        #pragma unroll
        for (int ni = 0; ni < 8; ni++) {
            int m = m0 + wm + mi * 16 + g;
            int n = n0 + wn + ni * 8 + t * 2;
            float b0 = __ldg(&bias[n]), b1 = __ldg(&bias[n + 1]);
            float v0 = acc[mi][ni][0] + b0;
            float v1 = acc[mi][ni][1] + b1;
            float v2 = acc[mi][ni][2] + b0;
            float v3 = acc[mi][ni][3] + b1;
            if (ROUND_OUT) { v0 = rnd(v0); v1 = rnd(v1); v2 = rnd(v2); v3 = rnd(v3); }
            C[(size_t)m * N + n]           = v0;
            C[(size_t)m * N + n + 1]       = v1;
            C[(size_t)(m + 8) * N + n]     = v2;
            C[(size_t)(m + 8) * N + n + 1] = v3;
        }
    }
}

// ---------------------------------------------------------------------------
// load Q a-fragments for 32 q-rows (2 m-tiles x 8 d-chunks) into registers.
// One-time LDG; values pre-rounded tf32 in g_q.
// ---------------------------------------------------------------------------
__device__ __forceinline__ void load_q_frags(uint32_t qa[2][8][4],
                                             int b, int h, int qbase,
                                             int g, int t) {
    #pragma unroll
    for (int mi = 0; mi < 2; mi++) {
        const float* qp = g_q + (size_t)(b * SEQ + qbase + mi * 16) * EMB + h * HDIM;
        #pragma unroll
        for (int d8 = 0; d8 < 8; d8++) {
            int c = d8 * 8;
            qa[mi][d8][0] = raw(qp[(size_t)g * EMB + c + t]);
            qa[mi][d8][1] = raw(qp[(size_t)(8 + g) * EMB + c + t]);
            qa[mi][d8][2] = raw(qp[(size_t)g * EMB + c + 4 + t]);
            qa[mi][d8][3] = raw(qp[(size_t)(8 + g) * EMB + c + 4 + t]);
        }
    }
}

// ---------------------------------------------------------------------------
// Kernel A: row sums of exp(QK^T * scale) -> g_inv = 1/sum.
// Q a-frags in registers; K tiles smem double-buffered. LDS/mma = 1.0.
// grid (SEQ/128, BH), 256 threads, warps 4m x 2n (32x32 tiles).
// ---------------------------------------------------------------------------
__global__ __launch_bounds__(256, 2)
void rowsum_tc() {
    extern __shared__ __align__(16) float sm[];
    float* Ks = sm;                       // [2][64][STR]
    __shared__ float s_red[128];

    const int bh = blockIdx.y;
    const int b  = bh / HEADS;
    const int h  = bh % HEADS;
    const int q0 = blockIdx.x * 128;
    const int tid = threadIdx.x;
    const int wid = tid >> 5;
    const int lane = tid & 31;
    const int wm = (wid >> 1) * 32;
    const int wn = (wid & 1) * 32;
    const int g = lane >> 2;
    const int t = lane & 3;

    if (tid < 128) s_red[tid] = 0.f;

    uint32_t qa[2][8][4];
    load_q_frags(qa, b, h, q0 + wm, g, t);

    #pragma unroll
    for (int i = 0; i < 4; i++) {
        int idx = tid + i * 256, r = idx >> 4, c4 = idx & 15;
        cp16(&Ks[r * STR + c4 * 4],
             g_k + (size_t)(b * SEQ + r) * EMB + h * HDIM + c4 * 4);
    }
    cp_commit();

    float rsum[2][2] = {};

    for (int kt = 0; kt < SEQ / 64; kt++) {
        if (kt + 1 < SEQ / 64) {
            float* Kn = Ks + ((kt + 1) & 1) * 64 * STR;
            const int r0 = (kt + 1) * 64;
            #pragma unroll
            for (int i = 0; i < 4; i++) {
                int idx = tid + i * 256, r = idx >> 4, c4 = idx & 15;
                cp16(&Kn[r * STR + c4 * 4],
                     g_k + (size_t)(b * SEQ + r0 + r) * EMB + h * HDIM + c4 * 4);
            }
            cp_commit();
            cp_wait1();
        } else {
            cp_wait0();
        }
        __syncthreads();

        const float* Kb = Ks + (kt & 1) * 64 * STR;
        float acc[2][4][4] = {};

        #pragma unroll
        for (int c0 = 0; c0 < 64; c0 += 32) {
            #pragma unroll
            for (int kk = 0; kk < 4; kk++) {
                const int kb = c0 + kk * 8;
                const int d8 = kb >> 3;
                uint32_t bb[4][2];
                #pragma unroll
                for (int ni = 0; ni < 4; ni++) {
                    int col = wn + ni * 8;
                    bb[ni][0] = raw(Kb[(col + g) * STR + kb + t]);
                    bb[ni][1] = raw(Kb[(col + g) * STR + kb + 4 + t]);
                }
                #pragma unroll
                for (int mi = 0; mi < 2; mi++)
                    #pragma unroll
                    for (int ni = 0; ni < 4; ni++)
                        mma_tf32(acc[mi][ni],
                                 qa[mi][d8][0], qa[mi][d8][1], qa[mi][d8][2], qa[mi][d8][3],
                                 bb[ni][0], bb[ni][1]);
            }
        }

        #pragma unroll
        for (int mi = 0; mi < 2; mi++)
            #pragma unroll
            for (int ni = 0; ni < 4; ni++) {
                rsum[mi][0] += __expf(acc[mi][ni][0] * SCALE_F)
                             + __expf(acc[mi][ni][1] * SCALE_F);
                rsum[mi][1] += __expf(acc[mi][ni][2] * SCALE_F)
                             + __expf(acc[mi][ni][3] * SCALE_F);
            }
        __syncthreads();
    }

    #pragma unroll
    for (int mi = 0; mi < 2; mi++)
        #pragma unroll
        for (int j = 0; j < 2; j++) {
            rsum[mi][j] += __shfl_xor_sync(0xffffffffu, rsum[mi][j], 1);
            rsum[mi][j] += __shfl_xor_sync(0xffffffffu, rsum[mi][j], 2);
        }

    if (t == 0) {
        #pragma unroll
        for (int mi = 0; mi < 2; mi++) {
            atomicAdd(&s_red[wm + mi * 16 + g],     rsum[mi][0]);
            atomicAdd(&s_red[wm + mi * 16 + 8 + g], rsum[mi][1]);
        }
    }
    __syncthreads();
    if (tid < 128)
        g_inv[(size_t)bh * SEQ + q0 + tid] = 1.0f / s_red[tid];
}

// ---------------------------------------------------------------------------
// Kernel B: flash pass. Q a-frags in registers; K/V smem double-buffered;
// p = exp(s)*inv staged in Ps smem (tf32-rounded) for coalesced write + PV.
// grid (SEQ/64, BH), 256 threads, scores warps 2m x 4n (32q x 16k).
// ---------------------------------------------------------------------------
__global__ __launch_bounds__(256, 2)
void flash_pv_tc(float* __restrict__ wbuf) {
    extern __shared__ __align__(16) float sm[];
    float* Ks = sm;                               // [2][64][STR]
    float* Vs = Ks + 2 * 64 * STR;                // [2][64][VSTR]
    float* Ps = Vs + 2 * 64 * VSTR;               // [64][STR]

    const int bh = blockIdx.y;
    const int b  = bh / HEADS;
    const int h  = bh % HEADS;
    const int q0 = blockIdx.x * 64;
    const int tid = threadIdx.x;
    const int wid = tid >> 5;
    const int lane = tid & 31;
    const int wm = (wid >> 2) * 32;
    const int wn = (wid & 3) * 16;
    const int g = lane >> 2;
    const int t = lane & 3;

    uint32_t qa[2][8][4];
    load_q_frags(qa, b, h, q0 + wm, g, t);

    float iv[2][2];
    #pragma unroll
    for (int mi = 0; mi < 2; mi++) {
        iv[mi][0] = g_inv[(size_t)bh * SEQ + q0 + wm + mi * 16 + g];
        iv[mi][1] = g_inv[(size_t)bh * SEQ + q0 + wm + mi * 16 + 8 + g];
    }

    #pragma unroll
    for (int i = 0; i < 4; i++) {
        int idx = tid + i * 256, r = idx >> 4, c4 = idx & 15;
        cp16(&Ks[r * STR + c4 * 4],
             g_k + (size_t)(b * SEQ + r) * EMB + h * HDIM + c4 * 4);
        cp16(&Vs[r * VSTR + c4 * 4],
             g_v + (size_t)(b * SEQ + r) * EMB + h * HDIM + c4 * 4);
    }
    cp_commit();

    float* prow = wbuf + (size_t)bh * SEQ * SEQ;
    float acc_o[2][2][4] = {};

    for (int kt = 0; kt < SEQ / 64; kt++) {
        if (kt + 1 < SEQ / 64) {
            const int nb = (kt + 1) & 1;
            const int r0 = (kt + 1) * 64;
            float* Kn = Ks + nb * 64 * STR;
            float* Vn = Vs + nb * 64 * VSTR;
            #pragma unroll
            for (int i = 0; i < 4; i++) {
                int idx = tid + i * 256, r = idx >> 4, c4 = idx & 15;
                cp16(&Kn[r * STR + c4 * 4],
                     g_k + (size_t)(b * SEQ + r0 + r) * EMB + h * HDIM + c4 * 4);
                cp16(&Vn[r * VSTR + c4 * 4],
                     g_v + (size_t)(b * SEQ + r0 + r) * EMB + h * HDIM + c4 * 4);
            }
            cp_commit();
            cp_wait1();
        } else {
            cp_wait0();
        }
        __syncthreads();

        const float* Kb = Ks + (kt & 1) * 64 * STR;
        const float* Vb = Vs + (kt & 1) * 64 * VSTR;

        float acc_s[2][2][4] = {};
        #pragma unroll
        for (int c0 = 0; c0 < 64; c0 += 32) {
            #pragma unroll
            for (int kk = 0; kk < 4; kk++) {
                const int kb = c0 + kk * 8;
                const int d8 = kb >> 3;
                uint32_t bb[2][2];
                #pragma unroll
                for (int ni = 0; ni < 2; ni++) {
                    int col = wn + ni * 8;
                    bb[ni][0] = raw(Kb[(col + g) * STR + kb + t]);
                    bb[ni][1] = raw(Kb[(col + g) * STR + kb + 4 + t]);
                }
                #pragma unroll
                for (int mi = 0; mi < 2; mi++)
                    #pragma unroll
                    for (int ni = 0; ni < 2; ni++)
                        mma_tf32(acc_s[mi][ni],
                                 qa[mi][d8][0], qa[mi][d8][1], qa[mi][d8][2], qa[mi][d8][3],
                                 bb[ni][0], bb[ni][1]);
            }
        }

        #pragma unroll
        for (int mi = 0; mi < 2; mi++) {
            #pragma unroll
            for (int ni = 0; ni < 2; ni++) {
                int m = wm + mi * 16 + g;
                int c = wn + ni * 8 + t * 2;
                Ps[m * STR + c]           = rnd(__expf(acc_s[mi][ni][0] * SCALE_F) * iv[mi][0]);
                Ps[m * STR + c + 1]       = rnd(__expf(acc_s[mi][ni][1] * SCALE_F) * iv[mi][0]);
                Ps[(m + 8) * STR + c]     = rnd(__expf(acc_s[mi][ni][2] * SCALE_F) * iv[mi][1]);
                Ps[(m + 8) * STR + c + 1] = rnd(__expf(acc_s[mi][ni][3] * SCALE_F) * iv[mi][1]);
            }
        }
        __syncthreads();

        #pragma unroll
        for (int i = 0; i < 4; i++) {
            int idx = tid + i * 256, r = idx >> 4, c4 = idx & 15;
            *(float4*)&prow[(size_t)(q0 + r) * SEQ + kt * 64 + c4 * 4] =
                *(const float4*)&Ps[r * STR + c4 * 4];
        }

        #pragma unroll
        for (int c0 = 0; c0 < 64; c0 += 32) {
            #pragma unroll
            for (int kk = 0; kk < 4; kk++) {
                const int kb = c0 + kk * 8;
                uint32_t a[2][4], bb[2][2];
                #pragma unroll
                for (int mi = 0; mi < 2; mi++) {
                    int row = wm + mi * 16;
                    a[mi][0] = raw(Ps[(row + g) * STR + kb + t]);
                    a[mi][1] = raw(Ps[(row + 8 + g) * STR + kb + t]);
                    a[mi][2] = raw(Ps[(row + g) * STR + kb + 4 + t]);
                    a[mi][3] = raw(Ps[(row + 8 + g) * STR + kb + 4 + t]);
                }
                #pragma unroll
                for (int ni = 0; ni < 2; ni++) {
                    int col = wn + ni * 8;
                    bb[ni][0] = raw(Vb[(kb + t) * VSTR + col + g]);
                    bb[ni][1] = raw(Vb[(kb + 4 + t) * VSTR + col + g]);
                }
                #pragma unroll
                for (int mi = 0; mi < 2; mi++)
                    #pragma unroll
                    for (int ni = 0; ni < 2; ni++)
                        mma_tf32(acc_o[mi][ni], a[mi][0], a[mi][1], a[mi][2], a[mi][3],
                                 bb[ni][0], bb[ni][1]);
            }
        }
        __syncthreads();
    }

    #pragma unroll
    for (int mi = 0; mi < 2; mi++) {
        #pragma unroll
        for (int ni = 0; ni < 2; ni++) {
            int m = q0 + wm + mi * 16 + g;
            int d = wn + ni * 8 + t * 2;
            g_att[(size_t)(b * SEQ + m) * EMB + h * HDIM + d]         = rnd(acc_o[mi][ni][0]);
            g_att[(size_t)(b * SEQ + m) * EMB + h * HDIM + d + 1]     = rnd(acc_o[mi][ni][1]);
            g_att[(size_t)(b * SEQ + m + 8) * EMB + h * HDIM + d]     = rnd(acc_o[mi][ni][2]);
            g_att[(size_t)(b * SEQ + m + 8) * EMB + h * HDIM + d + 1] = rnd(acc_o[mi][ni][3]);
        }
    }
}

// ---------------------------------------------------------------------------
// launch
// ---------------------------------------------------------------------------
extern "C" void kernel_launch(void* const* d_in, const int* in_sizes, int n_in,
                              void* d_out, int out_size) {
    (void)in_sizes; (void)n_in; (void)out_size;

    const float* hs = (const float*)d_in[0];
    const float* Wq = (const float*)d_in[1];
    const float* bq = (const float*)d_in[2];
    const float* Wk = (const float*)d_in[3];
    const float* bk = (const float*)d_in[4];
    const float* Wv = (const float*)d_in[5];
    const float* bv = (const float*)d_in[6];
    const float* Wo = (const float*)d_in[7];
    const float* bo = (const float*)d_in[8];

    float* out      = (float*)d_out;
    float* attn_out = out;
    float* wbuf     = out + (size_t)MTOK * EMB;

    float* dq, * dk, * dv, * datt, * dhsr, * dwq, * dwk, * dwv, * dwo;
    cudaGetSymbolAddress((void**)&dq,   g_q);
    cudaGetSymbolAddress((void**)&dk,   g_k);
    cudaGetSymbolAddress((void**)&dv,   g_v);
    cudaGetSymbolAddress((void**)&datt, g_att);
    cudaGetSymbolAddress((void**)&dhsr, g_hsr);
    cudaGetSymbolAddress((void**)&dwq,  g_wq);
    cudaGetSymbolAddress((void**)&dwk,  g_wk);
    cudaGetSymbolAddress((void**)&dwv,  g_wv);
    cudaGetSymbolAddress((void**)&dwo,  g_wo);

    const int smem_gemm  = (3 * 128 * PAD + 3 * 128 * PAD) * 4;                 // 110592
    const int smem_rsum  = (2 * 64 * STR) * 4;                                  // 34816
    const int smem_flash = (2 * 64 * STR + 2 * 64 * VSTR + 64 * STR) * 4;       // 89088

    cudaFuncSetAttribute(gemm_xwT_tc<true>,  cudaFuncAttributeMaxDynamicSharedMemorySize, smem_gemm);
    cudaFuncSetAttribute(gemm_xwT_tc<false>, cudaFuncAttributeMaxDynamicSharedMemorySize, smem_gemm);
    cudaFuncSetAttribute(rowsum_tc,   cudaFuncAttributeMaxDynamicSharedMemorySize, smem_rsum);
    cudaFuncSetAttribute(flash_pv_tc, cudaFuncAttributeMaxDynamicSharedMemorySize, smem_flash);

    // pre-round hs and weights to tf32 (idempotent w.r.t. fragment cvt)
    const int n4_hs = MTOK * EMB / 4;
    const int n4_w  = EMB * EMB / 4;
    round_tf32_kernel<<<(n4_hs + 255) / 256, 256>>>((const float4*)hs, (float4*)dhsr, n4_hs);
    round_tf32_kernel<<<(n4_w + 255) / 256, 256>>>((const float4*)Wq, (float4*)dwq, n4_w);
    round_tf32_kernel<<<(n4_w + 255) / 256, 256>>>((const float4*)Wk, (float4*)dwk, n4_w);
    round_tf32_kernel<<<(n4_w + 255) / 256, 256>>>((const float4*)Wv, (float4*)dwv, n4_w);
    round_tf32_kernel<<<(n4_w + 255) / 256, 256>>>((const float4*)Wo, (float4*)dwo, n4_w);

    dim3 gproj(EMB / 128, MTOK / 128);      // (6, 64)

    gemm_xwT_tc<true><<<gproj, 256, smem_gemm>>>(dhsr, dwq, bq, dq, MTOK, EMB, EMB);
    gemm_xwT_tc<true><<<gproj, 256, smem_gemm>>>(dhsr, dwk, bk, dk, MTOK, EMB, EMB);
    gemm_xwT_tc<true><<<gproj, 256, smem_gemm>>>(dhsr, dwv, bv, dv, MTOK, EMB, EMB);

    rowsum_tc<<<dim3(SEQ / 128, BH), 256, smem_rsum>>>();

    flash_pv_tc<<<dim3(SEQ / 64, BH), 256, smem_flash>>>(wbuf);

    gemm_xwT_tc<false><<<gproj, 256, smem_gemm>>>(datt, dwo, bo, attn_out, MTOK, EMB, EMB);
}

// round 11
// speedup vs baseline: 1.4651x; 1.0363x over previous
#include <cuda_runtime.h>
#include <cuda_bf16.h>
#include <math.h>
#include <stdint.h>

// ---------------------------------------------------------------------------
// ViT attention: TF32 mma.sync, pre-rounded tf32 operands, sigma-permuted
// Q/K layouts (vector fragment loads), fragment-major P staging, single-sync
// cp.async pipelines.
// B=4, S=2048, E=768, H=12, D=64.
// d_out = attn_output [4,2048,768] ++ attn_weights [4,12,2048,2048].
//
// sigma (within each d-group of 8): logical k index t -> position 2t,
// 4+t -> 2t+1. So a fragment pair (k=t, k=4+t) is contiguous (LDS.64/LDG.64).
// ---------------------------------------------------------------------------

#define BATCH     4
#define SEQ       2048
#define EMB       768
#define HEADS     12
#define HDIM      64
#define MTOK      (BATCH * SEQ)
#define BH        (BATCH * HEADS)
#define SCALE_F   0.125f

#define PAD       36      // projection smem stride
#define KSTR      72      // K/V tile stride (72%32=8 -> conflict-free LDS.64)
#define VSTR      72
#define PSBLK     132     // Ps words per (mt,chunk) block (128 + 4 pad)

// Scratch (device globals — no allocation allowed). All tf32-rounded.
// g_q/g_k are sigma-permuted along d; g_v/g_att plain.
__device__ float g_q[MTOK * EMB];
__device__ float g_k[MTOK * EMB];
__device__ float g_v[MTOK * EMB];
__device__ float g_att[MTOK * EMB];
__device__ float g_inv[BH * SEQ];
__device__ float g_hsr[MTOK * EMB];
__device__ float g_wq[EMB * EMB];
__device__ float g_wk[EMB * EMB];
__device__ float g_wv[EMB * EMB];
__device__ float g_wo[EMB * EMB];

// ---------------------------------------------------------------------------
__device__ __forceinline__ void cp16(void* s, const void* g) {
    uint32_t sa = (uint32_t)__cvta_generic_to_shared(s);
    asm volatile("cp.async.cg.shared.global [%0], [%1], 16;\n" :: "r"(sa), "l"(g));
}
__device__ __forceinline__ void cp_commit() {
    asm volatile("cp.async.commit_group;\n" ::: "memory");
}
__device__ __forceinline__ void cp_wait1() {
    asm volatile("cp.async.wait_group 1;\n" ::: "memory");
}
__device__ __forceinline__ void cp_wait0() {
    asm volatile("cp.async.wait_group 0;\n" ::: "memory");
}

__device__ __forceinline__ float rnd(float x) {
    float r;
    asm("cvt.rna.tf32.f32 %0, %1;" : "=f"(r) : "f"(x));
    return r;
}
__device__ __forceinline__ uint32_t raw(float x) { return __float_as_uint(x); }

__device__ __forceinline__ void mma_tf32(float c[4],
                                         uint32_t a0, uint32_t a1, uint32_t a2, uint32_t a3,
                                         uint32_t b0, uint32_t b1) {
    asm volatile(
        "mma.sync.aligned.m16n8k8.row.col.f32.tf32.tf32.f32 "
        "{%0,%1,%2,%3}, {%4,%5,%6,%7}, {%8,%9}, {%0,%1,%2,%3};\n"
        : "+f"(c[0]), "+f"(c[1]), "+f"(c[2]), "+f"(c[3])
        : "r"(a0), "r"(a1), "r"(a2), "r"(a3), "r"(b0), "r"(b1));
}

// ---------------------------------------------------------------------------
__global__ void round_tf32_kernel(const float4* __restrict__ in,
                                  float4* __restrict__ out, int n4) {
    int i = blockIdx.x * blockDim.x + threadIdx.x;
    if (i < n4) {
        float4 v = in[i];
        v.x = rnd(v.x); v.y = rnd(v.y); v.z = rnd(v.z); v.w = rnd(v.w);
        out[i] = v;
    }
}

// ---------------------------------------------------------------------------
// Projection GEMM: C = A @ W^T + bias. 128x128 tile, 8 warps, 3-stage
// cp.async, single sync per iteration.
// MODE 0: plain fp32 store. MODE 1: tf32-rounded, sigma-permuted (g_q/g_k).
// MODE 2: tf32-rounded plain (g_v).
// ---------------------------------------------------------------------------
template <int MODE>
__global__ __launch_bounds__(256, 2)
void gemm_xwT_tc(const float* __restrict__ A,
                 const float* __restrict__ W,
                 const float* __restrict__ bias,
                 float* __restrict__ C,
                 int M, int N, int K) {
    extern __shared__ __align__(16) float sm[];
    float (*As)[128][PAD] = (float (*)[128][PAD])sm;
    float (*Ws)[128][PAD] = (float (*)[128][PAD])(sm + 3 * 128 * PAD);

    const int m0 = blockIdx.y * 128;
    const int n0 = blockIdx.x * 128;
    const int tid = threadIdx.x;
    const int wid = tid >> 5;
    const int lane = tid & 31;
    const int wm = (wid >> 1) * 32;
    const int wn = (wid & 1) * 64;
    const int g = lane >> 2;
    const int t = lane & 3;
    const int nk = K >> 5;

    float acc[2][8][4] = {};

    #pragma unroll
    for (int s = 0; s < 2; s++) {
        const int k0 = s * 32;
        #pragma unroll
        for (int i = 0; i < 4; i++) {
            int idx = tid + i * 256, r = idx >> 3, c4 = idx & 7;
            cp16(&As[s][r][c4 * 4], A + (size_t)(m0 + r) * K + k0 + c4 * 4);
        }
        #pragma unroll
        for (int i = 0; i < 4; i++) {
            int idx = tid + i * 256, r = idx >> 3, c4 = idx & 7;
            cp16(&Ws[s][r][c4 * 4], W + (size_t)(n0 + r) * K + k0 + c4 * 4);
        }
        cp_commit();
    }

    for (int kt = 0; kt < nk; kt++) {
        cp_wait1();                 // stage kt complete (pending <= 1)
        __syncthreads();            // all warps done with buf (kt-1)%3

        if (kt + 2 < nk) {
            const int sb = (kt + 2) % 3;
            const int k0 = (kt + 2) * 32;
            #pragma unroll
            for (int i = 0; i < 4; i++) {
                int idx = tid + i * 256, r = idx >> 3, c4 = idx & 7;
                cp16(&As[sb][r][c4 * 4], A + (size_t)(m0 + r) * K + k0 + c4 * 4);
            }
            #pragma unroll
            for (int i = 0; i < 4; i++) {
                int idx = tid + i * 256, r = idx >> 3, c4 = idx & 7;
                cp16(&Ws[sb][r][c4 * 4], W + (size_t)(n0 + r) * K + k0 + c4 * 4);
            }
        }
        cp_commit();                // always commit (keeps group accounting)

        const int buf = kt % 3;
        #pragma unroll
        for (int kk = 0; kk < 4; kk++) {
            const int kb = kk * 8;
            uint32_t a[2][4], b[8][2];
            #pragma unroll
            for (int mi = 0; mi < 2; mi++) {
                int row = wm + mi * 16;
                a[mi][0] = raw(As[buf][row + g][kb + t]);
                a[mi][1] = raw(As[buf][row + 8 + g][kb + t]);
                a[mi][2] = raw(As[buf][row + g][kb + 4 + t]);
                a[mi][3] = raw(As[buf][row + 8 + g][kb + 4 + t]);
            }
            #pragma unroll
            for (int ni = 0; ni < 8; ni++) {
                int col = wn + ni * 8;
                b[ni][0] = raw(Ws[buf][col + g][kb + t]);
                b[ni][1] = raw(Ws[buf][col + g][kb + 4 + t]);
            }
            #pragma unroll
            for (int mi = 0; mi < 2; mi++)
                #pragma unroll
                for (int ni = 0; ni < 8; ni++)
                    mma_tf32(acc[mi][ni], a[mi][0], a[mi][1], a[mi][2], a[mi][3],
                             b[ni][0], b[ni][1]);
        }
    }

    #pragma unroll
    for (int mi = 0; mi < 2; mi++) {
        #pragma unroll
        for (int ni = 0; ni < 8; ni++) {
            int m = m0 + wm + mi * 16 + g;
            int n = n0 + wn + ni * 8 + t * 2;           // even
            float b0 = __ldg(&bias[n]), b1 = __ldg(&bias[n + 1]);
            float v0 = acc[mi][ni][0] + b0;
            float v1 = acc[mi][ni][1] + b1;
            float v2 = acc[mi][ni][2] + b0;
            float v3 = acc[mi][ni][3] + b1;
            if (MODE == 0) {
                C[(size_t)m * N + n]           = v0;
                C[(size_t)m * N + n + 1]       = v1;
                C[(size_t)(m + 8) * N + n]     = v2;
                C[(size_t)(m + 8) * N + n + 1] = v3;
            } else if (MODE == 2) {
                C[(size_t)m * N + n]           = rnd(v0);
                C[(size_t)m * N + n + 1]       = rnd(v1);
                C[(size_t)(m + 8) * N + n]     = rnd(v2);
                C[(size_t)(m + 8) * N + n + 1] = rnd(v3);
            } else {
                // sigma permute within 8-group: pos = ((n&3)<<1)|((n>>2)&1)
                int nb = n & ~7;
                int p0 = nb + (((n & 3) << 1) | ((n >> 2) & 1));
                int p1 = p0 + 2;                         // for n+1 (same j)
                C[(size_t)m * N + p0]       = rnd(v0);
                C[(size_t)m * N + p1]       = rnd(v1);
                C[(size_t)(m + 8) * N + p0] = rnd(v2);
                C[(size_t)(m + 8) * N + p1] = rnd(v3);
            }
        }
    }
}

// ---------------------------------------------------------------------------
// Q a-fragments for 32 rows from sigma-permuted g_q: LDG.64 pairs.
// ---------------------------------------------------------------------------
__device__ __forceinline__ void load_q_frags(uint32_t qa[2][8][4],
                                             int b, int h, int qbase,
                                             int g, int t) {
    #pragma unroll
    for (int mi = 0; mi < 2; mi++) {
        const float* qp = g_q + (size_t)(b * SEQ + qbase + mi * 16) * EMB + h * HDIM;
        #pragma unroll
        for (int d8 = 0; d8 < 8; d8++) {
            int c = d8 * 8 + 2 * t;
            float2 lo = *(const float2*)&qp[(size_t)g * EMB + c];
            float2 hi = *(const float2*)&qp[(size_t)(8 + g) * EMB + c];
            qa[mi][d8][0] = raw(lo.x);   // k = t
            qa[mi][d8][1] = raw(hi.x);
            qa[mi][d8][2] = raw(lo.y);   // k = 4+t
            qa[mi][d8][3] = raw(hi.y);
        }
    }
}

// ---------------------------------------------------------------------------
// rowsum: g_inv = 1/rowsum(exp(QK^T*scale)). Q in regs; K smem (sigma'd),
// b-frags via LDS.64; single sync per iteration.
// grid (SEQ/128, BH), 8 warps 4m x 2n.
// ---------------------------------------------------------------------------
__global__ __launch_bounds__(256, 2)
void rowsum_tc() {
    extern __shared__ __align__(16) float sm[];
    float* Ks = sm;                       // [2][64][KSTR]
    __shared__ float s_red[128];

    const int bh = blockIdx.y;
    const int b  = bh / HEADS;
    const int h  = bh % HEADS;
    const int q0 = blockIdx.x * 128;
    const int tid = threadIdx.x;
    const int wid = tid >> 5;
    const int lane = tid & 31;
    const int wm = (wid >> 1) * 32;
    const int wn = (wid & 1) * 32;
    const int g = lane >> 2;
    const int t = lane & 3;

    if (tid < 128) s_red[tid] = 0.f;

    #pragma unroll
    for (int i = 0; i < 4; i++) {
        int idx = tid + i * 256, r = idx >> 4, c4 = idx & 15;
        cp16(&Ks[r * KSTR + c4 * 4],
             g_k + (size_t)(b * SEQ + r) * EMB + h * HDIM + c4 * 4);
    }
    cp_commit();

    uint32_t qa[2][8][4];
    load_q_frags(qa, b, h, q0 + wm, g, t);

    float rsum[2][2] = {};

    for (int kt = 0; kt < SEQ / 64; kt++) {
        cp_wait0();
        __syncthreads();

        if (kt + 1 < SEQ / 64) {
            float* Kn = Ks + ((kt + 1) & 1) * 64 * KSTR;
            const int r0 = (kt + 1) * 64;
            #pragma unroll
            for (int i = 0; i < 4; i++) {
                int idx = tid + i * 256, r = idx >> 4, c4 = idx & 15;
                cp16(&Kn[r * KSTR + c4 * 4],
                     g_k + (size_t)(b * SEQ + r0 + r) * EMB + h * HDIM + c4 * 4);
            }
            cp_commit();
        }

        const float* Kb = Ks + (kt & 1) * 64 * KSTR;
        float acc[2][4][4] = {};

        #pragma unroll
        for (int d8 = 0; d8 < 8; d8++) {
            const int kb = d8 * 8;
            uint32_t bb[4][2];
            #pragma unroll
            for (int ni = 0; ni < 4; ni++) {
                int col = wn + ni * 8;
                float2 kv = *(const float2*)&Kb[(col + g) * KSTR + kb + 2 * t];
                bb[ni][0] = raw(kv.x);
                bb[ni][1] = raw(kv.y);
            }
            #pragma unroll
            for (int mi = 0; mi < 2; mi++)
                #pragma unroll
                for (int ni = 0; ni < 4; ni++)
                    mma_tf32(acc[mi][ni],
                             qa[mi][d8][0], qa[mi][d8][1], qa[mi][d8][2], qa[mi][d8][3],
                             bb[ni][0], bb[ni][1]);
        }

        #pragma unroll
        for (int mi = 0; mi < 2; mi++)
            #pragma unroll
            for (int ni = 0; ni < 4; ni++) {
                rsum[mi][0] += __expf(acc[mi][ni][0] * SCALE_F)
                             + __expf(acc[mi][ni][1] * SCALE_F);
                rsum[mi][1] += __expf(acc[mi][ni][2] * SCALE_F)
                             + __expf(acc[mi][ni][3] * SCALE_F);
            }
    }

    #pragma unroll
    for (int mi = 0; mi < 2; mi++)
        #pragma unroll
        for (int j = 0; j < 2; j++) {
            rsum[mi][j] += __shfl_xor_sync(0xffffffffu, rsum[mi][j], 1);
            rsum[mi][j] += __shfl_xor_sync(0xffffffffu, rsum[mi][j], 2);
        }

    if (t == 0) {
        #pragma unroll
        for (int mi = 0; mi < 2; mi++) {
            atomicAdd(&s_red[wm + mi * 16 + g],     rsum[mi][0]);
            atomicAdd(&s_red[wm + mi * 16 + 8 + g], rsum[mi][1]);
        }
    }
    __syncthreads();
    if (tid < 128)
        g_inv[(size_t)bh * SEQ + q0 + tid] = 1.0f / s_red[tid];
}

// ---------------------------------------------------------------------------
// flash: recompute scores (Q regs, K LDS.64), p = exp(s)*inv written to gmem
// directly from c-frags AND to frag-major Ps; PV a-frags via LDS.128.
// grid (SEQ/64, BH), 8 warps: wm=(wid>>2)*32, wn=(wid&3)*16.
// Ps layout: addr = (mt*8 + chunk)*PSBLK + (g*4 + t')*4 + j
//   j: 0=(row g,k t) 1=(row 8+g,k t) 2=(row g,k 4+t) 3=(row 8+g,k 4+t)
// ---------------------------------------------------------------------------
__global__ __launch_bounds__(256, 2)
void flash_pv_tc(float* __restrict__ wbuf) {
    extern __shared__ __align__(16) float sm[];
    float* Ks = sm;                               // [2][64][KSTR]
    float* Vs = Ks + 2 * 64 * KSTR;               // [2][64][VSTR]
    float* Ps = Vs + 2 * 64 * VSTR;               // [32][PSBLK]

    const int bh = blockIdx.y;
    const int b  = bh / HEADS;
    const int h  = bh % HEADS;
    const int q0 = blockIdx.x * 64;
    const int tid = threadIdx.x;
    const int wid = tid >> 5;
    const int lane = tid & 31;
    const int wm = (wid >> 2) * 32;
    const int wn = (wid & 3) * 16;
    const int g = lane >> 2;
    const int t = lane & 3;

    #pragma unroll
    for (int i = 0; i < 4; i++) {
        int idx = tid + i * 256, r = idx >> 4, c4 = idx & 15;
        cp16(&Ks[r * KSTR + c4 * 4],
             g_k + (size_t)(b * SEQ + r) * EMB + h * HDIM + c4 * 4);
        cp16(&Vs[r * VSTR + c4 * 4],
             g_v + (size_t)(b * SEQ + r) * EMB + h * HDIM + c4 * 4);
    }
    cp_commit();

    uint32_t qa[2][8][4];
    load_q_frags(qa, b, h, q0 + wm, g, t);

    float iv[2][2];
    #pragma unroll
    for (int mi = 0; mi < 2; mi++) {
        iv[mi][0] = g_inv[(size_t)bh * SEQ + q0 + wm + mi * 16 + g];
        iv[mi][1] = g_inv[(size_t)bh * SEQ + q0 + wm + mi * 16 + 8 + g];
    }

    float* prow = wbuf + (size_t)bh * SEQ * SEQ;
    float acc_o[2][2][4] = {};

    // producer Ps slot constants
    const int tp0 = (2 * t) & 3;          // t' for col c0
    const int tp1 = (2 * t + 1) & 3;      // t' for col c0+1
    const int j0  = 2 * (t >> 1);

    for (int kt = 0; kt < SEQ / 64; kt++) {
        cp_wait0();
        __syncthreads();                  // pipeline + Ps-consumed barrier

        if (kt + 1 < SEQ / 64) {
            const int nb = (kt + 1) & 1;
            const int r0 = (kt + 1) * 64;
            float* Kn = Ks + nb * 64 * KSTR;
            float* Vn = Vs + nb * 64 * VSTR;
            #pragma unroll
            for (int i = 0; i < 4; i++) {
                int idx = tid + i * 256, r = idx >> 4, c4 = idx & 15;
                cp16(&Kn[r * KSTR + c4 * 4],
                     g_k + (size_t)(b * SEQ + r0 + r) * EMB + h * HDIM + c4 * 4);
                cp16(&Vn[r * VSTR + c4 * 4],
                     g_v + (size_t)(b * SEQ + r0 + r) * EMB + h * HDIM + c4 * 4);
            }
            cp_commit();
        }

        const float* Kb = Ks + (kt & 1) * 64 * KSTR;
        const float* Vb = Vs + (kt & 1) * 64 * VSTR;

        // scores
        float acc_s[2][2][4] = {};
        #pragma unroll
        for (int d8 = 0; d8 < 8; d8++) {
            const int kb = d8 * 8;
            uint32_t bb[2][2];
            #pragma unroll
            for (int ni = 0; ni < 2; ni++) {
                int col = wn + ni * 8;
                float2 kv = *(const float2*)&Kb[(col + g) * KSTR + kb + 2 * t];
                bb[ni][0] = raw(kv.x);
                bb[ni][1] = raw(kv.y);
            }
            #pragma unroll
            for (int mi = 0; mi < 2; mi++)
                #pragma unroll
                for (int ni = 0; ni < 2; ni++)
                    mma_tf32(acc_s[mi][ni],
                             qa[mi][d8][0], qa[mi][d8][1], qa[mi][d8][2], qa[mi][d8][3],
                             bb[ni][0], bb[ni][1]);
        }

        // p = exp(s)*inv: write gmem (direct) + Ps (frag-major)
        #pragma unroll
        for (int mi = 0; mi < 2; mi++) {
            const int mt = (wm >> 4) + mi;
            const int r0g = q0 + wm + mi * 16 + g;
            #pragma unroll
            for (int ni = 0; ni < 2; ni++) {
                const int c0 = wn + ni * 8 + 2 * t;
                const int chunk = (wn >> 3) + ni;
                float p00 = rnd(__expf(acc_s[mi][ni][0] * SCALE_F) * iv[mi][0]);
                float p01 = rnd(__expf(acc_s[mi][ni][1] * SCALE_F) * iv[mi][0]);
                float p10 = rnd(__expf(acc_s[mi][ni][2] * SCALE_F) * iv[mi][1]);
                float p11 = rnd(__expf(acc_s[mi][ni][3] * SCALE_F) * iv[mi][1]);
                // gmem weights (row-major, 8B stores, full 32B sectors/quad)
                *(float2*)&prow[(size_t)r0g * SEQ + kt * 64 + c0]       = make_float2(p00, p01);
                *(float2*)&prow[(size_t)(r0g + 8) * SEQ + kt * 64 + c0] = make_float2(p10, p11);
                // Ps frag-major (STS.64 x2)
                float* pb = &Ps[(mt * 8 + chunk) * PSBLK];
                *(float2*)&pb[(g * 4 + tp0) * 4 + j0] = make_float2(p00, p10);
                *(float2*)&pb[(g * 4 + tp1) * 4 + j0] = make_float2(p01, p11);
            }
        }
        __syncthreads();                  // Ps ready (cross-warp within wm group)

        // O += p @ V  (a: LDS.128 from Ps; b: V [k][n])
        #pragma unroll
        for (int d8 = 0; d8 < 8; d8++) {
            const int kb = d8 * 8;
            uint32_t a[2][4];
            #pragma unroll
            for (int mi = 0; mi < 2; mi++) {
                const int mt = (wm >> 4) + mi;
                float4 av = *(const float4*)&Ps[(mt * 8 + d8) * PSBLK + lane * 4];
                a[mi][0] = raw(av.x);
                a[mi][1] = raw(av.y);
                a[mi][2] = raw(av.z);
                a[mi][3] = raw(av.w);
            }
            uint32_t bb[2][2];
            #pragma unroll
            for (int ni = 0; ni < 2; ni++) {
                int col = wn + ni * 8;
                bb[ni][0] = raw(Vb[(kb + t) * VSTR + col + g]);
                bb[ni][1] = raw(Vb[(kb + 4 + t) * VSTR + col + g]);
            }
            #pragma unroll
            for (int mi = 0; mi < 2; mi++)
                #pragma unroll
                for (int ni = 0; ni < 2; ni++)
                    mma_tf32(acc_o[mi][ni], a[mi][0], a[mi][1], a[mi][2], a[mi][3],
                             bb[ni][0], bb[ni][1]);
        }
    }

    #pragma unroll
    for (int mi = 0; mi < 2; mi++) {
        #pragma unroll
        for (int ni = 0; ni < 2; ni++) {
            int m = q0 + wm + mi * 16 + g;
            int d = wn + ni * 8 + t * 2;
            g_att[(size_t)(b * SEQ + m) * EMB + h * HDIM + d]         = rnd(acc_o[mi][ni][0]);
            g_att[(size_t)(b * SEQ + m) * EMB + h * HDIM + d + 1]     = rnd(acc_o[mi][ni][1]);
            g_att[(size_t)(b * SEQ + m + 8) * EMB + h * HDIM + d]     = rnd(acc_o[mi][ni][2]);
            g_att[(size_t)(b * SEQ + m + 8) * EMB + h * HDIM + d + 1] = rnd(acc_o[mi][ni][3]);
        }
    }
}

// ---------------------------------------------------------------------------
// launch
// ---------------------------------------------------------------------------
extern "C" void kernel_launch(void* const* d_in, const int* in_sizes, int n_in,
                              void* d_out, int out_size) {
    (void)in_sizes; (void)n_in; (void)out_size;

    const float* hs = (const float*)d_in[0];
    const float* Wq = (const float*)d_in[1];
    const float* bq = (const float*)d_in[2];
    const float* Wk = (const float*)d_in[3];
    const float* bk = (const float*)d_in[4];
    const float* Wv = (const float*)d_in[5];
    const float* bv = (const float*)d_in[6];
    const float* Wo = (const float*)d_in[7];
    const float* bo = (const float*)d_in[8];

    float* out      = (float*)d_out;
    float* attn_out = out;
    float* wbuf     = out + (size_t)MTOK * EMB;

    float* dq, * dk, * dv, * datt, * dhsr, * dwq, * dwk, * dwv, * dwo;
    cudaGetSymbolAddress((void**)&dq,   g_q);
    cudaGetSymbolAddress((void**)&dk,   g_k);
    cudaGetSymbolAddress((void**)&dv,   g_v);
    cudaGetSymbolAddress((void**)&datt, g_att);
    cudaGetSymbolAddress((void**)&dhsr, g_hsr);
    cudaGetSymbolAddress((void**)&dwq,  g_wq);
    cudaGetSymbolAddress((void**)&dwk,  g_wk);
    cudaGetSymbolAddress((void**)&dwv,  g_wv);
    cudaGetSymbolAddress((void**)&dwo,  g_wo);

    const int smem_gemm  = (3 * 128 * PAD + 3 * 128 * PAD) * 4;                 // 110592
    const int smem_rsum  = (2 * 64 * KSTR) * 4;                                 // 36864
    const int smem_flash = (2 * 64 * KSTR + 2 * 64 * VSTR + 32 * PSBLK) * 4;    // 90624

    cudaFuncSetAttribute(gemm_xwT_tc<0>, cudaFuncAttributeMaxDynamicSharedMemorySize, smem_gemm);
    cudaFuncSetAttribute(gemm_xwT_tc<1>, cudaFuncAttributeMaxDynamicSharedMemorySize, smem_gemm);
    cudaFuncSetAttribute(gemm_xwT_tc<2>, cudaFuncAttributeMaxDynamicSharedMemorySize, smem_gemm);
    cudaFuncSetAttribute(rowsum_tc,   cudaFuncAttributeMaxDynamicSharedMemorySize, smem_rsum);
    cudaFuncSetAttribute(flash_pv_tc, cudaFuncAttributeMaxDynamicSharedMemorySize, smem_flash);

    const int n4_hs = MTOK * EMB / 4;
    const int n4_w  = EMB * EMB / 4;
    round_tf32_kernel<<<(n4_hs + 255) / 256, 256>>>((const float4*)hs, (float4*)dhsr, n4_hs);
    round_tf32_kernel<<<(n4_w + 255) / 256, 256>>>((const float4*)Wq, (float4*)dwq, n4_w);
    round_tf32_kernel<<<(n4_w + 255) / 256, 256>>>((const float4*)Wk, (float4*)dwk, n4_w);
    round_tf32_kernel<<<(n4_w + 255) / 256, 256>>>((const float4*)Wv, (float4*)dwv, n4_w);
    round_tf32_kernel<<<(n4_w + 255) / 256, 256>>>((const float4*)Wo, (float4*)dwo, n4_w);

    dim3 gproj(EMB / 128, MTOK / 128);      // (6, 64)

    gemm_xwT_tc<1><<<gproj, 256, smem_gemm>>>(dhsr, dwq, bq, dq, MTOK, EMB, EMB);
    gemm_xwT_tc<1><<<gproj, 256, smem_gemm>>>(dhsr, dwk, bk, dk, MTOK, EMB, EMB);
    gemm_xwT_tc<2><<<gproj, 256, smem_gemm>>>(dhsr, dwv, bv, dv, MTOK, EMB, EMB);

    rowsum_tc<<<dim3(SEQ / 128, BH), 256, smem_rsum>>>();

    flash_pv_tc<<<dim3(SEQ / 64, BH), 256, smem_flash>>>(wbuf);

    gemm_xwT_tc<0><<<gproj, 256, smem_gemm>>>(datt, dwo, bo, attn_out, MTOK, EMB, EMB);
}